// round 2
// baseline (speedup 1.0000x reference)
#include <cuda_runtime.h>
#include <cstdint>

#define DIM      512
#define KTOP     5
#define NTHREADS 512
#define NWARPS   (NTHREADS / 32)
#define GROUP    4   // float4s per thread per iteration (16 elements)

// Tie-break identical to jax.lax.top_k: higher value first, then lower index.
__device__ __forceinline__ bool better(float av, int ai, float bv, int bi) {
    return (av > bv) || (av == bv && ai < bi);
}

// Insert (nv, ni) into a descending-sorted top-5 list held in registers.
__device__ __forceinline__ void insert5(float (&v)[KTOP], int (&ix)[KTOP],
                                        float nv, int ni) {
    if (!better(nv, ni, v[KTOP - 1], ix[KTOP - 1])) return;
    v[KTOP - 1] = nv;
    ix[KTOP - 1] = ni;
#pragma unroll
    for (int j = KTOP - 1; j > 0; --j) {
        if (better(v[j], ix[j], v[j - 1], ix[j - 1])) {
            float tv = v[j]; v[j] = v[j - 1]; v[j - 1] = tv;
            int   ti = ix[j]; ix[j] = ix[j - 1]; ix[j - 1] = ti;
        } else {
            break;
        }
    }
}

// Merge partner lane's top-5 list into ours via xor-shuffle butterfly step.
__device__ __forceinline__ void warp_merge_step(float (&v)[KTOP], int (&ix)[KTOP],
                                                int off) {
    float ov[KTOP];
    int   oi[KTOP];
#pragma unroll
    for (int j = 0; j < KTOP; ++j) {
        ov[j] = __shfl_xor_sync(0xFFFFFFFFu, v[j], off);
        oi[j] = __shfl_xor_sync(0xFFFFFFFFu, ix[j], off);
    }
#pragma unroll
    for (int j = 0; j < KTOP; ++j) insert5(v, ix, ov[j], oi[j]);
}

__device__ __forceinline__ float max4(float4 z) {
    return fmaxf(fmaxf(z.x, z.y), fmaxf(z.z, z.w));
}

__device__ __forceinline__ void scan4(float (&v)[KTOP], int (&ix)[KTOP],
                                      float4 z, int elem_base) {
    insert5(v, ix, z.x, elem_base);
    insert5(v, ix, z.y, elem_base + 1);
    insert5(v, ix, z.z, elem_base + 2);
    insert5(v, ix, z.w, elem_base + 3);
}

__global__ __launch_bounds__(NTHREADS)
void fused_topk_attn_kernel(const float* __restrict__ sp_z,
                            const float* __restrict__ sp_w,
                            const float* __restrict__ encoded,
                            float* __restrict__ out,       // [B, DIM]
                            float* __restrict__ attn_out,  // [B, KTOP] or nullptr
                            float* __restrict__ idx_out,   // [B, KTOP] or nullptr
                            int V) {
    const int row  = blockIdx.x;
    const int tid  = threadIdx.x;
    const int lane = tid & 31;
    const int warp = tid >> 5;

    __shared__ float s_wv[NWARPS][KTOP];
    __shared__ int   s_wi[NWARPS][KTOP];
    __shared__ int   s_idx[KTOP];
    __shared__ float s_red[NWARPS][KTOP];
    __shared__ float s_scores[KTOP];

    // ---------------- Phase 1: per-row top-5 of sp_z[row, :] ----------------
    float v[KTOP];
    int   ix[KTOP];
#pragma unroll
    for (int k = 0; k < KTOP; ++k) { v[k] = -__int_as_float(0x7F800000); ix[k] = 0x7FFFFFFF; }

    const size_t rowbase = (size_t)row * (size_t)V;

    if ((V & 3) == 0) {
        const float4* zrow = reinterpret_cast<const float4*>(sp_z + rowbase);
        const int nv4      = V >> 2;
        const int per_iter = NTHREADS * GROUP;
        const int nfull    = nv4 / per_iter;

        for (int it = 0; it < nfull; ++it) {
            const int base = it * per_iter + tid;
            // 4 independent strided 16B loads: MLP=4, coalesced across the block.
            float4 z0 = __ldcs(zrow + base);
            float4 z1 = __ldcs(zrow + base +     NTHREADS);
            float4 z2 = __ldcs(zrow + base + 2 * NTHREADS);
            float4 z3 = __ldcs(zrow + base + 3 * NTHREADS);

            // Branchless group-max filter: 15 FMNMX + 1 compare per 16 elems.
            float m = fmaxf(fmaxf(max4(z0), max4(z1)), fmaxf(max4(z2), max4(z3)));

            if (m > v[KTOP - 1]) {  // rare: a top-5 candidate is in this group.
                // Per-thread indices are strictly increasing, so equal-valued
                // later elements lose lax.top_k's lower-index tie-break; the
                // strict '>' guard above is exact.
                scan4(v, ix, z0, (base               ) << 2);
                scan4(v, ix, z1, (base +     NTHREADS) << 2);
                scan4(v, ix, z2, (base + 2 * NTHREADS) << 2);
                scan4(v, ix, z3, (base + 3 * NTHREADS) << 2);
            }
        }
        // Tail float4s.
        for (int i = nfull * per_iter + tid; i < nv4; i += NTHREADS) {
            float4 z = __ldcs(zrow + i);
            if (max4(z) > v[KTOP - 1]) scan4(v, ix, z, i << 2);
        }
    } else {
        for (int j = tid; j < V; j += NTHREADS) {
            float z = __ldg(sp_z + rowbase + j);
            if (z > v[KTOP - 1]) insert5(v, ix, z, j);
        }
    }

    // Warp-level butterfly merge: every lane ends with the warp's top-5.
#pragma unroll
    for (int off = 16; off; off >>= 1) warp_merge_step(v, ix, off);

    if (lane == 0) {
#pragma unroll
        for (int k = 0; k < KTOP; ++k) { s_wv[warp][k] = v[k]; s_wi[warp][k] = ix[k]; }
    }
    __syncthreads();

    // Cross-warp merge in warp 0 (16 candidate lists on lanes 0..15).
    if (warp == 0) {
        float mv[KTOP];
        int   mi[KTOP];
        if (lane < NWARPS) {
#pragma unroll
            for (int k = 0; k < KTOP; ++k) { mv[k] = s_wv[lane][k]; mi[k] = s_wi[lane][k]; }
        } else {
#pragma unroll
            for (int k = 0; k < KTOP; ++k) { mv[k] = -__int_as_float(0x7F800000); mi[k] = 0x7FFFFFFF; }
        }
#pragma unroll
        for (int off = 8; off; off >>= 1) warp_merge_step(mv, mi, off);
        if (lane == 0) {
#pragma unroll
            for (int k = 0; k < KTOP; ++k) s_idx[k] = mi[k];
        }
    }
    __syncthreads();

    // ---------------- Phase 2: gather + attention ----------------
    // Thread tid owns output dimension d = tid (DIM == NTHREADS == 512).
    const int d = tid;
    const float enc = __ldg(encoded + (size_t)row * DIM + d);

    float w[KTOP];
    float partial[KTOP];
#pragma unroll
    for (int k = 0; k < KTOP; ++k) {
        w[k] = __ldg(sp_w + (size_t)s_idx[k] * DIM + d);
        partial[k] = w[k] * enc;
    }

    // Block reduction of the 5 dot products.
#pragma unroll
    for (int off = 16; off; off >>= 1) {
#pragma unroll
        for (int k = 0; k < KTOP; ++k)
            partial[k] += __shfl_down_sync(0xFFFFFFFFu, partial[k], off);
    }
    if (lane == 0) {
#pragma unroll
        for (int k = 0; k < KTOP; ++k) s_red[warp][k] = partial[k];
    }
    __syncthreads();
    if (tid < KTOP) {
        float s = 0.f;
#pragma unroll
        for (int wq = 0; wq < NWARPS; ++wq) s += s_red[wq][tid];
        s_scores[tid] = s;
    }
    __syncthreads();

    // Softmax over K=5, computed redundantly per thread (cheap, avoids a sync).
    float sc[KTOP];
#pragma unroll
    for (int k = 0; k < KTOP; ++k) sc[k] = s_scores[k];
    float m = sc[0];
#pragma unroll
    for (int k = 1; k < KTOP; ++k) m = fmaxf(m, sc[k]);
    float e[KTOP];
    float esum = 0.f;
#pragma unroll
    for (int k = 0; k < KTOP; ++k) { e[k] = expf(sc[k] - m); esum += e[k]; }
    const float inv = 1.0f / esum;

    float acc = 0.f;
#pragma unroll
    for (int k = 0; k < KTOP; ++k) acc += w[k] * (e[k] * inv);
    out[(size_t)row * DIM + d] = acc;

    if (tid < KTOP) {
        if (attn_out) attn_out[(size_t)row * KTOP + tid] = e[tid] * inv;
        if (idx_out)  idx_out[(size_t)row * KTOP + tid] = (float)s_idx[tid];
    }
}

extern "C" void kernel_launch(void* const* d_in, const int* in_sizes, int n_in,
                              void* d_out, int out_size) {
    const float* sp_z    = (const float*)d_in[0];  // [B, V]
    const float* sp_w    = (const float*)d_in[1];  // [V, DIM]
    const float* encoded = (const float*)d_in[2];  // [B, DIM]

    const int B = in_sizes[2] / DIM;
    const int V = in_sizes[0] / B;

    float* out = (float*)d_out;
    // Tuple output flattened in return order: out [B*DIM], attn [B*K], indices [B*K].
    float* attn_out = nullptr;
    float* idx_out  = nullptr;
    if (out_size >= B * (DIM + KTOP))     attn_out = out + (size_t)B * DIM;
    if (out_size >= B * (DIM + 2 * KTOP)) idx_out  = out + (size_t)B * (DIM + KTOP);

    fused_topk_attn_kernel<<<B, NTHREADS>>>(sp_z, sp_w, encoded,
                                            out, attn_out, idx_out, V);
}

// round 3
// speedup vs baseline: 1.1410x; 1.1410x over previous
#include <cuda_runtime.h>
#include <cstdint>

#define DIM      512
#define KTOP     5
#define NTHREADS 512
#define NWARPS   (NTHREADS / 32)
#define GROUP    4                    // float4s per thread per iteration (16 elems)
#define PER_ITER (NTHREADS * GROUP)   // float4s per block iteration

#define NEG_INF (-__int_as_float(0x7F800000))

// Tie-break identical to jax.lax.top_k: higher value first, then lower index.
__device__ __forceinline__ bool better(float av, int ai, float bv, int bi) {
    return (av > bv) || (av == bv && ai < bi);
}

// Insert (nv, ni) into a descending-sorted top-5 list held in registers.
__device__ __forceinline__ void insert5(float (&v)[KTOP], int (&ix)[KTOP],
                                        float nv, int ni) {
    if (!better(nv, ni, v[KTOP - 1], ix[KTOP - 1])) return;
    v[KTOP - 1] = nv;
    ix[KTOP - 1] = ni;
#pragma unroll
    for (int j = KTOP - 1; j > 0; --j) {
        if (better(v[j], ix[j], v[j - 1], ix[j - 1])) {
            float tv = v[j]; v[j] = v[j - 1]; v[j - 1] = tv;
            int   ti = ix[j]; ix[j] = ix[j - 1]; ix[j - 1] = ti;
        } else {
            break;
        }
    }
}

// Merge partner lane's top-5 list into ours via xor-shuffle butterfly step.
__device__ __forceinline__ void warp_merge_step(float (&v)[KTOP], int (&ix)[KTOP],
                                                int off) {
    float ov[KTOP];
    int   oi[KTOP];
#pragma unroll
    for (int j = 0; j < KTOP; ++j) {
        ov[j] = __shfl_xor_sync(0xFFFFFFFFu, v[j], off);
        oi[j] = __shfl_xor_sync(0xFFFFFFFFu, ix[j], off);
    }
#pragma unroll
    for (int j = 0; j < KTOP; ++j) insert5(v, ix, ov[j], oi[j]);
}

__device__ __forceinline__ float max4(float4 z) {
    return fmaxf(fmaxf(z.x, z.y), fmaxf(z.z, z.w));
}

__device__ __forceinline__ void scan4(float (&v)[KTOP], int (&ix)[KTOP],
                                      float4 z, int elem_base) {
    insert5(v, ix, z.x, elem_base);
    insert5(v, ix, z.y, elem_base + 1);
    insert5(v, ix, z.z, elem_base + 2);
    insert5(v, ix, z.w, elem_base + 3);
}

__global__ __launch_bounds__(NTHREADS, 2)
void fused_topk_attn_kernel(const float* __restrict__ sp_z,
                            const float* __restrict__ sp_w,
                            const float* __restrict__ encoded,
                            float* __restrict__ out,       // [B, DIM]
                            float* __restrict__ attn_out,  // [B, KTOP] or nullptr
                            float* __restrict__ idx_out,   // [B, KTOP] or nullptr
                            int V) {
    const int row  = blockIdx.x;
    const int tid  = threadIdx.x;
    const int lane = tid & 31;
    const int warp = tid >> 5;

    __shared__ float s_wv[NWARPS][KTOP];
    __shared__ int   s_wi[NWARPS][KTOP];
    __shared__ float s_t;                 // block-wide safe filter threshold
    __shared__ int   s_idx[KTOP];
    __shared__ float s_red[NWARPS][KTOP];
    __shared__ float s_scores[KTOP];

    float v[KTOP];
    int   ix[KTOP];
#pragma unroll
    for (int k = 0; k < KTOP; ++k) { v[k] = NEG_INF; ix[k] = 0x7FFFFFFF; }

    const size_t rowbase = (size_t)row * (size_t)V;

    if ((V & 3) == 0) {
        const float4* zrow = reinterpret_cast<const float4*>(sp_z + rowbase);
        const int nv4 = V >> 2;

        // ---- Warm-up: full guarded scan of the first PER_ITER float4s ----
#pragma unroll
        for (int g = 0; g < GROUP; ++g) {
            const int i = g * NTHREADS + tid;
            if (i < nv4) {
                float4 z = __ldcs(zrow + i);
                if (max4(z) > v[KTOP - 1]) scan4(v, ix, z, i << 2);
            }
        }

        // ---- Compute block-prefix top-5 on COPIES; broadcast 5th value ----
        {
            float mv[KTOP];
            int   mi[KTOP];
#pragma unroll
            for (int k = 0; k < KTOP; ++k) { mv[k] = v[k]; mi[k] = ix[k]; }
#pragma unroll
            for (int off = 16; off; off >>= 1) warp_merge_step(mv, mi, off);
            if (lane == 0) {
#pragma unroll
                for (int k = 0; k < KTOP; ++k) { s_wv[warp][k] = mv[k]; s_wi[warp][k] = mi[k]; }
            }
            __syncthreads();
            if (warp == 0) {
                if (lane < NWARPS) {
#pragma unroll
                    for (int k = 0; k < KTOP; ++k) { mv[k] = s_wv[lane][k]; mi[k] = s_wi[lane][k]; }
                } else {
#pragma unroll
                    for (int k = 0; k < KTOP; ++k) { mv[k] = NEG_INF; mi[k] = 0x7FFFFFFF; }
                }
#pragma unroll
                for (int off = 8; off; off >>= 1) warp_merge_step(mv, mi, off);
                if (lane == 0) s_t = mv[KTOP - 1];
            }
            __syncthreads();
        }
        const float t = s_t;   // prefix 5th-best <= global 5th-best: safe filter

        // ---- Main filtered loop with register double-buffer prefetch ----
        const int nfull = (nv4 > PER_ITER) ? (nv4 - PER_ITER) / PER_ITER : 0;
        int base = PER_ITER + tid;

        float4 a0, a1, a2, a3;
        if (nfull > 0) {
            a0 = __ldcs(zrow + base);
            a1 = __ldcs(zrow + base +     NTHREADS);
            a2 = __ldcs(zrow + base + 2 * NTHREADS);
            a3 = __ldcs(zrow + base + 3 * NTHREADS);
        }
        for (int it = 0; it < nfull; ++it) {
            const int nbase = base + PER_ITER;
            float4 b0, b1, b2, b3;
            if (it + 1 < nfull) {   // prefetch next group before the data branch
                b0 = __ldcs(zrow + nbase);
                b1 = __ldcs(zrow + nbase +     NTHREADS);
                b2 = __ldcs(zrow + nbase + 2 * NTHREADS);
                b3 = __ldcs(zrow + nbase + 3 * NTHREADS);
            }
            const float m = fmaxf(fmaxf(max4(a0), max4(a1)),
                                  fmaxf(max4(a2), max4(a3)));
            if (m >= t) {  // rare after warm-up (~25 hits per block total)
                scan4(v, ix, a0, (base               ) << 2);
                scan4(v, ix, a1, (base +     NTHREADS) << 2);
                scan4(v, ix, a2, (base + 2 * NTHREADS) << 2);
                scan4(v, ix, a3, (base + 3 * NTHREADS) << 2);
            }
            a0 = b0; a1 = b1; a2 = b2; a3 = b3;
            base = nbase;
        }
        // Tail float4s.
        for (int i = PER_ITER + nfull * PER_ITER + tid; i < nv4; i += NTHREADS) {
            float4 z = __ldcs(zrow + i);
            if (max4(z) >= t) scan4(v, ix, z, i << 2);
        }
    } else {
        for (int j = tid; j < V; j += NTHREADS) {
            float z = __ldg(sp_z + rowbase + j);
            if (z > v[KTOP - 1]) insert5(v, ix, z, j);
        }
    }

    // ---- Final exact block merge of per-thread (disjoint) lists ----
#pragma unroll
    for (int off = 16; off; off >>= 1) warp_merge_step(v, ix, off);
    if (lane == 0) {
#pragma unroll
        for (int k = 0; k < KTOP; ++k) { s_wv[warp][k] = v[k]; s_wi[warp][k] = ix[k]; }
    }
    __syncthreads();
    if (warp == 0) {
        float mv[KTOP];
        int   mi[KTOP];
        if (lane < NWARPS) {
#pragma unroll
            for (int k = 0; k < KTOP; ++k) { mv[k] = s_wv[lane][k]; mi[k] = s_wi[lane][k]; }
        } else {
#pragma unroll
            for (int k = 0; k < KTOP; ++k) { mv[k] = NEG_INF; mi[k] = 0x7FFFFFFF; }
        }
#pragma unroll
        for (int off = 8; off; off >>= 1) warp_merge_step(mv, mi, off);
        if (lane == 0) {
#pragma unroll
            for (int k = 0; k < KTOP; ++k) s_idx[k] = mi[k];
        }
    }
    __syncthreads();

    // ---------------- Phase 2: gather + attention ----------------
    const int d = tid;   // DIM == NTHREADS == 512
    const float enc = __ldg(encoded + (size_t)row * DIM + d);

    float w[KTOP];
    float partial[KTOP];
#pragma unroll
    for (int k = 0; k < KTOP; ++k) {
        w[k] = __ldg(sp_w + (size_t)s_idx[k] * DIM + d);
        partial[k] = w[k] * enc;
    }
#pragma unroll
    for (int off = 16; off; off >>= 1) {
#pragma unroll
        for (int k = 0; k < KTOP; ++k)
            partial[k] += __shfl_down_sync(0xFFFFFFFFu, partial[k], off);
    }
    if (lane == 0) {
#pragma unroll
        for (int k = 0; k < KTOP; ++k) s_red[warp][k] = partial[k];
    }
    __syncthreads();
    if (tid < KTOP) {
        float s = 0.f;
#pragma unroll
        for (int wq = 0; wq < NWARPS; ++wq) s += s_red[wq][tid];
        s_scores[tid] = s;
    }
    __syncthreads();

    float sc[KTOP];
#pragma unroll
    for (int k = 0; k < KTOP; ++k) sc[k] = s_scores[k];
    float m = sc[0];
#pragma unroll
    for (int k = 1; k < KTOP; ++k) m = fmaxf(m, sc[k]);
    float e[KTOP];
    float esum = 0.f;
#pragma unroll
    for (int k = 0; k < KTOP; ++k) { e[k] = expf(sc[k] - m); esum += e[k]; }
    const float inv = 1.0f / esum;

    float acc = 0.f;
#pragma unroll
    for (int k = 0; k < KTOP; ++k) acc += w[k] * (e[k] * inv);
    out[(size_t)row * DIM + d] = acc;

    if (tid < KTOP) {
        if (attn_out) attn_out[(size_t)row * KTOP + tid] = e[tid] * inv;
        if (idx_out)  idx_out[(size_t)row * KTOP + tid] = (float)s_idx[tid];
    }
}

extern "C" void kernel_launch(void* const* d_in, const int* in_sizes, int n_in,
                              void* d_out, int out_size) {
    const float* sp_z    = (const float*)d_in[0];  // [B, V]
    const float* sp_w    = (const float*)d_in[1];  // [V, DIM]
    const float* encoded = (const float*)d_in[2];  // [B, DIM]

    const int B = in_sizes[2] / DIM;
    const int V = in_sizes[0] / B;

    float* out = (float*)d_out;
    float* attn_out = nullptr;
    float* idx_out  = nullptr;
    if (out_size >= B * (DIM + KTOP))     attn_out = out + (size_t)B * DIM;
    if (out_size >= B * (DIM + 2 * KTOP)) idx_out  = out + (size_t)B * (DIM + KTOP);

    fused_topk_attn_kernel<<<B, NTHREADS>>>(sp_z, sp_w, encoded,
                                            out, attn_out, idx_out, V);
}

// round 4
// speedup vs baseline: 3.7692x; 3.3035x over previous
#include <cuda_runtime.h>
#include <cstdint>

#define DIM      512
#define KTOP     5
#define NTHREADS 512
#define NWARPS   (NTHREADS / 32)
#define GROUP    4                    // float4s per thread per iteration (16 elems)
#define PER_ITER (NTHREADS * GROUP)   // float4s per block iteration
#define GRP_MAX  1024                 // hit-group buffer entries
#define CAND_MAX 2048                 // candidate buffer entries

#define NEG_INF (-__int_as_float(0x7F800000))

// Tie-break identical to jax.lax.top_k: higher value first, then lower index.
__device__ __forceinline__ bool better(float av, int ai, float bv, int bi) {
    return (av > bv) || (av == bv && ai < bi);
}

// Insert (nv, ni) into a descending-sorted top-5 list (only used on ~30 candidates).
__device__ __forceinline__ void insert5(float (&v)[KTOP], int (&ix)[KTOP],
                                        float nv, int ni) {
    if (!better(nv, ni, v[KTOP - 1], ix[KTOP - 1])) return;
    v[KTOP - 1] = nv;
    ix[KTOP - 1] = ni;
#pragma unroll
    for (int j = KTOP - 1; j > 0; --j) {
        if (better(v[j], ix[j], v[j - 1], ix[j - 1])) {
            float tv = v[j]; v[j] = v[j - 1]; v[j - 1] = tv;
            int   ti = ix[j]; ix[j] = ix[j - 1]; ix[j - 1] = ti;
        } else {
            break;
        }
    }
}

__device__ __forceinline__ void warp_merge_step(float (&v)[KTOP], int (&ix)[KTOP],
                                                int off) {
    float ov[KTOP];
    int   oi[KTOP];
#pragma unroll
    for (int j = 0; j < KTOP; ++j) {
        ov[j] = __shfl_xor_sync(0xFFFFFFFFu, v[j], off);
        oi[j] = __shfl_xor_sync(0xFFFFFFFFu, ix[j], off);
    }
#pragma unroll
    for (int j = 0; j < KTOP; ++j) insert5(v, ix, ov[j], oi[j]);
}

__device__ __forceinline__ float max4(float4 z) {
    return fmaxf(fmaxf(z.x, z.y), fmaxf(z.z, z.w));
}

__global__ __launch_bounds__(NTHREADS)
void fused_topk_attn_kernel(const float* __restrict__ sp_z,
                            const float* __restrict__ sp_w,
                            const float* __restrict__ encoded,
                            float* __restrict__ out,       // [B, DIM]
                            float* __restrict__ attn_out,  // [B, KTOP] or nullptr
                            float* __restrict__ idx_out,   // [B, KTOP] or nullptr
                            int V) {
    const int row  = blockIdx.x;
    const int tid  = threadIdx.x;
    const int lane = tid & 31;
    const int warp = tid >> 5;

    __shared__ float s_warpmax[NWARPS];
    __shared__ float s_t;
    __shared__ int   s_gcnt;
    __shared__ int   s_cnt;
    __shared__ int   s_gbase[GRP_MAX];
    __shared__ float s_cand_v[CAND_MAX];
    __shared__ int   s_cand_i[CAND_MAX];
    __shared__ int   s_idx[KTOP];
    __shared__ float s_red[NWARPS][KTOP];
    __shared__ float s_scores[KTOP];

    if (tid == 0) { s_gcnt = 0; s_cnt = 0; }

    const size_t rowbase = (size_t)row * (size_t)V;
    const float4* zrow   = reinterpret_cast<const float4*>(sp_z + rowbase);
    const int nv4 = V >> 2;            // V % 4 == 0 for this problem (50000)

    // ---- 1. Threshold: 5th-largest warp-max of the first PER_ITER float4s ----
    // Each of the top-5 warp-maxes is a distinct element, so t <= global 5th:
    // filtering with (z >= t) provably keeps every global top-5 element.
    float tmax = NEG_INF;
#pragma unroll
    for (int g = 0; g < GROUP; ++g) {
        const int i = g * NTHREADS + tid;
        if (i < nv4) tmax = fmaxf(tmax, max4(__ldg(zrow + i)));
    }
#pragma unroll
    for (int off = 16; off; off >>= 1)
        tmax = fmaxf(tmax, __shfl_xor_sync(0xFFFFFFFFu, tmax, off));
    if (lane == 0) s_warpmax[warp] = tmax;
    __syncthreads();

    if (warp == 0) {
        float wv = (lane < NWARPS) ? s_warpmax[lane] : NEG_INF;
        float tcur = NEG_INF;
#pragma unroll
        for (int r = 0; r < KTOP; ++r) {
            float m = wv;
#pragma unroll
            for (int off = 16; off; off >>= 1)
                m = fmaxf(m, __shfl_xor_sync(0xFFFFFFFFu, m, off));
            unsigned msk = __ballot_sync(0xFFFFFFFFu, wv == m);
            int leader = __ffs(msk) - 1;
            if (lane == leader) wv = NEG_INF;   // remove exactly one holder
            tcur = m;
        }
        if (lane == 0) s_t = tcur;
    }
    __syncthreads();
    const float t = s_t;

    // ---- 2. Hot loop: branchless max filter, push GROUP BASE only on hit ----
    const int nfull = nv4 / PER_ITER;
    for (int it = 0; it < nfull; ++it) {
        const int base = it * PER_ITER + tid;
        float4 z0 = __ldcs(zrow + base);
        float4 z1 = __ldcs(zrow + base +     NTHREADS);
        float4 z2 = __ldcs(zrow + base + 2 * NTHREADS);
        float4 z3 = __ldcs(zrow + base + 3 * NTHREADS);
        const float m = fmaxf(fmaxf(max4(z0), max4(z1)),
                              fmaxf(max4(z2), max4(z3)));
        if (m >= t) {                        // rare; body is 3 instrs, no sorting
            int p = atomicAdd(&s_gcnt, 1);
            if (p < GRP_MAX) s_gbase[p] = base;
        }
    }
    // Tail float4s: push surviving elements directly as candidates.
    for (int i = nfull * PER_ITER + tid; i < nv4; i += NTHREADS) {
        float4 z = __ldcs(zrow + i);
        if (max4(z) >= t) {
            const float zz[4] = {z.x, z.y, z.z, z.w};
#pragma unroll
            for (int r = 0; r < 4; ++r) {
                if (zz[r] >= t) {
                    int p = atomicAdd(&s_cnt, 1);
                    if (p < CAND_MAX) { s_cand_v[p] = zz[r]; s_cand_i[p] = (i << 2) + r; }
                }
            }
        }
    }
    __syncthreads();

    // ---- 3. Expand hit groups: ballot-compact elements >= t into candidates ----
    {
        const int ng = min(s_gcnt, GRP_MAX);
        for (int g = warp; g < ng; g += NWARPS) {
            const int base = s_gbase[g];
            float z = NEG_INF;
            int eidx = 0;
            if (lane < 16) {
                const int q = lane >> 2, r = lane & 3;
                const int fi = base + q * NTHREADS;      // float4 index
                eidx = (fi << 2) + r;
                z = __ldg(sp_z + rowbase + eidx);
            }
            const unsigned msk = __ballot_sync(0xFFFFFFFFu, z >= t);
            const int cnt = __popc(msk);
            int posbase = 0;
            if (lane == 0 && cnt) posbase = atomicAdd(&s_cnt, cnt);
            posbase = __shfl_sync(0xFFFFFFFFu, posbase, 0);
            const int off = __popc(msk & ((1u << lane) - 1));
            if ((z >= t) && (posbase + off) < CAND_MAX) {
                s_cand_v[posbase + off] = z;
                s_cand_i[posbase + off] = eidx;
            }
        }
    }
    __syncthreads();

    // ---- 4. Exact top-5 (with lax.top_k tie-break) over ~30 candidates ----
    if (warp == 0) {
        float v[KTOP];
        int   ix[KTOP];
#pragma unroll
        for (int k = 0; k < KTOP; ++k) { v[k] = NEG_INF; ix[k] = 0x7FFFFFFF; }
        const int n = min(s_cnt, CAND_MAX);
        for (int c = lane; c < n; c += 32)
            insert5(v, ix, s_cand_v[c], s_cand_i[c]);
#pragma unroll
        for (int off = 16; off; off >>= 1) warp_merge_step(v, ix, off);
        if (lane == 0) {
#pragma unroll
            for (int k = 0; k < KTOP; ++k) s_idx[k] = ix[k];
        }
    }
    __syncthreads();

    // ---------------- Phase 2: gather + attention ----------------
    const int d = tid;   // DIM == NTHREADS == 512
    const float enc = __ldg(encoded + (size_t)row * DIM + d);

    float w[KTOP];
    float partial[KTOP];
#pragma unroll
    for (int k = 0; k < KTOP; ++k) {
        w[k] = __ldg(sp_w + (size_t)s_idx[k] * DIM + d);
        partial[k] = w[k] * enc;
    }
#pragma unroll
    for (int off = 16; off; off >>= 1) {
#pragma unroll
        for (int k = 0; k < KTOP; ++k)
            partial[k] += __shfl_down_sync(0xFFFFFFFFu, partial[k], off);
    }
    if (lane == 0) {
#pragma unroll
        for (int k = 0; k < KTOP; ++k) s_red[warp][k] = partial[k];
    }
    __syncthreads();
    if (tid < KTOP) {
        float s = 0.f;
#pragma unroll
        for (int wq = 0; wq < NWARPS; ++wq) s += s_red[wq][tid];
        s_scores[tid] = s;
    }
    __syncthreads();

    float sc[KTOP];
#pragma unroll
    for (int k = 0; k < KTOP; ++k) sc[k] = s_scores[k];
    float mx = sc[0];
#pragma unroll
    for (int k = 1; k < KTOP; ++k) mx = fmaxf(mx, sc[k]);
    float e[KTOP];
    float esum = 0.f;
#pragma unroll
    for (int k = 0; k < KTOP; ++k) { e[k] = expf(sc[k] - mx); esum += e[k]; }
    const float inv = 1.0f / esum;

    float acc = 0.f;
#pragma unroll
    for (int k = 0; k < KTOP; ++k) acc += w[k] * (e[k] * inv);
    out[(size_t)row * DIM + d] = acc;

    if (tid < KTOP) {
        if (attn_out) attn_out[(size_t)row * KTOP + tid] = e[tid] * inv;
        if (idx_out)  idx_out[(size_t)row * KTOP + tid] = (float)s_idx[tid];
    }
}

extern "C" void kernel_launch(void* const* d_in, const int* in_sizes, int n_in,
                              void* d_out, int out_size) {
    const float* sp_z    = (const float*)d_in[0];  // [B, V]
    const float* sp_w    = (const float*)d_in[1];  // [V, DIM]
    const float* encoded = (const float*)d_in[2];  // [B, DIM]

    const int B = in_sizes[2] / DIM;
    const int V = in_sizes[0] / B;

    float* out = (float*)d_out;
    float* attn_out = nullptr;
    float* idx_out  = nullptr;
    if (out_size >= B * (DIM + KTOP))     attn_out = out + (size_t)B * DIM;
    if (out_size >= B * (DIM + 2 * KTOP)) idx_out  = out + (size_t)B * (DIM + KTOP);

    fused_topk_attn_kernel<<<B, NTHREADS>>>(sp_z, sp_w, encoded,
                                            out, attn_out, idx_out, V);
}

// round 5
// speedup vs baseline: 3.7807x; 1.0031x over previous
#include <cuda_runtime.h>
#include <cstdint>

#define DIM      512
#define KTOP     5
#define NTHREADS 512
#define NWARPS   (NTHREADS / 32)
#define GROUP    8                    // float4s per thread per iteration (32 elems)
#define PER_ITER (NTHREADS * GROUP)   // float4s per block iteration
#define GRP_MAX  1024                 // hit-group buffer entries
#define CAND_MAX 2048                 // candidate buffer entries

#define NEG_INF (-__int_as_float(0x7F800000))

// Tie-break identical to jax.lax.top_k: higher value first, then lower index.
__device__ __forceinline__ bool better(float av, int ai, float bv, int bi) {
    return (av > bv) || (av == bv && ai < bi);
}

// Insert (nv, ni) into a descending-sorted top-5 list (only used on ~30 candidates).
__device__ __forceinline__ void insert5(float (&v)[KTOP], int (&ix)[KTOP],
                                        float nv, int ni) {
    if (!better(nv, ni, v[KTOP - 1], ix[KTOP - 1])) return;
    v[KTOP - 1] = nv;
    ix[KTOP - 1] = ni;
#pragma unroll
    for (int j = KTOP - 1; j > 0; --j) {
        if (better(v[j], ix[j], v[j - 1], ix[j - 1])) {
            float tv = v[j]; v[j] = v[j - 1]; v[j - 1] = tv;
            int   ti = ix[j]; ix[j] = ix[j - 1]; ix[j - 1] = ti;
        } else {
            break;
        }
    }
}

__device__ __forceinline__ void warp_merge_step(float (&v)[KTOP], int (&ix)[KTOP],
                                                int off) {
    float ov[KTOP];
    int   oi[KTOP];
#pragma unroll
    for (int j = 0; j < KTOP; ++j) {
        ov[j] = __shfl_xor_sync(0xFFFFFFFFu, v[j], off);
        oi[j] = __shfl_xor_sync(0xFFFFFFFFu, ix[j], off);
    }
#pragma unroll
    for (int j = 0; j < KTOP; ++j) insert5(v, ix, ov[j], oi[j]);
}

__device__ __forceinline__ float max4(float4 z) {
    return fmaxf(fmaxf(z.x, z.y), fmaxf(z.z, z.w));
}

__global__ __launch_bounds__(NTHREADS)
void fused_topk_attn_kernel(const float* __restrict__ sp_z,
                            const float* __restrict__ sp_w,
                            const float* __restrict__ encoded,
                            float* __restrict__ out,       // [B, DIM]
                            float* __restrict__ attn_out,  // [B, KTOP] or nullptr
                            float* __restrict__ idx_out,   // [B, KTOP] or nullptr
                            int V) {
    const int row  = blockIdx.x;
    const int tid  = threadIdx.x;
    const int lane = tid & 31;
    const int warp = tid >> 5;

    __shared__ float s_warpmax[NWARPS];
    __shared__ float s_t;
    __shared__ int   s_gcnt;
    __shared__ int   s_cnt;
    __shared__ int   s_gbase[GRP_MAX];
    __shared__ float s_cand_v[CAND_MAX];
    __shared__ int   s_cand_i[CAND_MAX];
    __shared__ int   s_idx[KTOP];
    __shared__ float s_red[NWARPS][KTOP];
    __shared__ float s_scores[KTOP];

    if (tid == 0) { s_gcnt = 0; s_cnt = 0; }

    const size_t rowbase = (size_t)row * (size_t)V;
    const float4* zrow   = reinterpret_cast<const float4*>(sp_z + rowbase);
    const int nv4 = V >> 2;            // V % 4 == 0 for this problem (50000)

    // ---- 1. Threshold: 5th-largest warp-max over the first 2048 float4s ----
    // The top-5 warp-maxes are 5 distinct elements, so t <= global 5th:
    // filtering with (z >= t) provably keeps every global top-5 element.
    float tmax = NEG_INF;
#pragma unroll
    for (int g = 0; g < 4; ++g) {
        const int i = g * NTHREADS + tid;
        if (i < nv4) tmax = fmaxf(tmax, max4(__ldg(zrow + i)));
    }
#pragma unroll
    for (int off = 16; off; off >>= 1)
        tmax = fmaxf(tmax, __shfl_xor_sync(0xFFFFFFFFu, tmax, off));
    if (lane == 0) s_warpmax[warp] = tmax;
    __syncthreads();

    if (warp == 0) {
        float wv = (lane < NWARPS) ? s_warpmax[lane] : NEG_INF;
        float tcur = NEG_INF;
#pragma unroll
        for (int r = 0; r < KTOP; ++r) {
            float m = wv;
#pragma unroll
            for (int off = 16; off; off >>= 1)
                m = fmaxf(m, __shfl_xor_sync(0xFFFFFFFFu, m, off));
            unsigned msk = __ballot_sync(0xFFFFFFFFu, wv == m);
            int leader = __ffs(msk) - 1;
            if (lane == leader) wv = NEG_INF;   // remove exactly one holder
            tcur = m;
        }
        if (lane == 0) s_t = tcur;
    }
    __syncthreads();
    const float t = s_t;

    // ---- 2. Hot loop: 8 independent LDG.128 in flight, one predicated push ----
    const int nfull = nv4 / PER_ITER;
    for (int it = 0; it < nfull; ++it) {
        const int base = it * PER_ITER + tid;
        float4 z0 = __ldcs(zrow + base);
        float4 z1 = __ldcs(zrow + base +     NTHREADS);
        float4 z2 = __ldcs(zrow + base + 2 * NTHREADS);
        float4 z3 = __ldcs(zrow + base + 3 * NTHREADS);
        float4 z4 = __ldcs(zrow + base + 4 * NTHREADS);
        float4 z5 = __ldcs(zrow + base + 5 * NTHREADS);
        float4 z6 = __ldcs(zrow + base + 6 * NTHREADS);
        float4 z7 = __ldcs(zrow + base + 7 * NTHREADS);
        const float m = fmaxf(
            fmaxf(fmaxf(max4(z0), max4(z1)), fmaxf(max4(z2), max4(z3))),
            fmaxf(fmaxf(max4(z4), max4(z5)), fmaxf(max4(z6), max4(z7))));
        if (m >= t) {                        // rare; body is 3 instrs, no sorting
            int p = atomicAdd(&s_gcnt, 1);
            if (p < GRP_MAX) s_gbase[p] = base;
        }
    }
    // Tail float4s: push surviving elements directly as candidates.
    for (int i = nfull * PER_ITER + tid; i < nv4; i += NTHREADS) {
        float4 z = __ldcs(zrow + i);
        if (max4(z) >= t) {
            const float zz[4] = {z.x, z.y, z.z, z.w};
#pragma unroll
            for (int r = 0; r < 4; ++r) {
                if (zz[r] >= t) {
                    int p = atomicAdd(&s_cnt, 1);
                    if (p < CAND_MAX) { s_cand_v[p] = zz[r]; s_cand_i[p] = (i << 2) + r; }
                }
            }
        }
    }
    __syncthreads();

    // ---- 3. Expand hit groups (32 elems = 1 warp): ballot-compact >= t ----
    {
        const int ng = min(s_gcnt, GRP_MAX);
        for (int g = warp; g < ng; g += NWARPS) {
            const int base = s_gbase[g];
            const int q = lane >> 2, r = lane & 3;
            const int fi = base + q * NTHREADS;          // float4 index
            const int eidx = (fi << 2) + r;
            const float z = __ldg(sp_z + rowbase + eidx);
            const unsigned msk = __ballot_sync(0xFFFFFFFFu, z >= t);
            const int cnt = __popc(msk);
            int posbase = 0;
            if (lane == 0 && cnt) posbase = atomicAdd(&s_cnt, cnt);
            posbase = __shfl_sync(0xFFFFFFFFu, posbase, 0);
            const int off = __popc(msk & ((1u << lane) - 1));
            if ((z >= t) && (posbase + off) < CAND_MAX) {
                s_cand_v[posbase + off] = z;
                s_cand_i[posbase + off] = eidx;
            }
        }
    }
    __syncthreads();

    // ---- 4. Exact top-5 (with lax.top_k tie-break) over ~30 candidates ----
    if (warp == 0) {
        float v[KTOP];
        int   ix[KTOP];
#pragma unroll
        for (int k = 0; k < KTOP; ++k) { v[k] = NEG_INF; ix[k] = 0x7FFFFFFF; }
        const int n = min(s_cnt, CAND_MAX);
        for (int c = lane; c < n; c += 32)
            insert5(v, ix, s_cand_v[c], s_cand_i[c]);
#pragma unroll
        for (int off = 16; off; off >>= 1) warp_merge_step(v, ix, off);
        if (lane == 0) {
#pragma unroll
            for (int k = 0; k < KTOP; ++k) s_idx[k] = ix[k];
        }
    }
    __syncthreads();

    // ---------------- Phase 2: gather + attention ----------------
    const int d = tid;   // DIM == NTHREADS == 512
    const float enc = __ldg(encoded + (size_t)row * DIM + d);

    float w[KTOP];
    float partial[KTOP];
#pragma unroll
    for (int k = 0; k < KTOP; ++k) {
        w[k] = __ldg(sp_w + (size_t)s_idx[k] * DIM + d);
        partial[k] = w[k] * enc;
    }
#pragma unroll
    for (int off = 16; off; off >>= 1) {
#pragma unroll
        for (int k = 0; k < KTOP; ++k)
            partial[k] += __shfl_down_sync(0xFFFFFFFFu, partial[k], off);
    }
    if (lane == 0) {
#pragma unroll
        for (int k = 0; k < KTOP; ++k) s_red[warp][k] = partial[k];
    }
    __syncthreads();
    if (tid < KTOP) {
        float s = 0.f;
#pragma unroll
        for (int wq = 0; wq < NWARPS; ++wq) s += s_red[wq][tid];
        s_scores[tid] = s;
    }
    __syncthreads();

    float sc[KTOP];
#pragma unroll
    for (int k = 0; k < KTOP; ++k) sc[k] = s_scores[k];
    float mx = sc[0];
#pragma unroll
    for (int k = 1; k < KTOP; ++k) mx = fmaxf(mx, sc[k]);
    float e[KTOP];
    float esum = 0.f;
#pragma unroll
    for (int k = 0; k < KTOP; ++k) { e[k] = expf(sc[k] - mx); esum += e[k]; }
    const float inv = 1.0f / esum;

    float acc = 0.f;
#pragma unroll
    for (int k = 0; k < KTOP; ++k) acc += w[k] * (e[k] * inv);
    out[(size_t)row * DIM + d] = acc;

    if (tid < KTOP) {
        if (attn_out) attn_out[(size_t)row * KTOP + tid] = e[tid] * inv;
        if (idx_out)  idx_out[(size_t)row * KTOP + tid] = (float)s_idx[tid];
    }
}

extern "C" void kernel_launch(void* const* d_in, const int* in_sizes, int n_in,
                              void* d_out, int out_size) {
    const float* sp_z    = (const float*)d_in[0];  // [B, V]
    const float* sp_w    = (const float*)d_in[1];  // [V, DIM]
    const float* encoded = (const float*)d_in[2];  // [B, DIM]

    const int B = in_sizes[2] / DIM;
    const int V = in_sizes[0] / B;

    float* out = (float*)d_out;
    float* attn_out = nullptr;
    float* idx_out  = nullptr;
    if (out_size >= B * (DIM + KTOP))     attn_out = out + (size_t)B * DIM;
    if (out_size >= B * (DIM + 2 * KTOP)) idx_out  = out + (size_t)B * (DIM + KTOP);

    fused_topk_attn_kernel<<<B, NTHREADS>>>(sp_z, sp_w, encoded,
                                            out, attn_out, idx_out, V);
}

// round 6
// speedup vs baseline: 4.0726x; 1.0772x over previous
#include <cuda_runtime.h>
#include <cstdint>

#define DIM      512
#define KTOP     5
#define NTHREADS 512
#define NWARPS   (NTHREADS / 32)
#define GROUP    4                    // float4s per thread per iteration (16 elems)
#define PER_ITER (NTHREADS * GROUP)   // float4s per block iteration
#define GRP_MAX  1024                 // hit-group buffer entries
#define CAND_MAX 2048                 // candidate buffer entries

#define NEG_INF (-__int_as_float(0x7F800000))

// Tie-break identical to jax.lax.top_k: higher value first, then lower index.
__device__ __forceinline__ bool better(float av, int ai, float bv, int bi) {
    return (av > bv) || (av == bv && ai < bi);
}

// Insert (nv, ni) into a descending-sorted top-5 list (cold path only).
__device__ __forceinline__ void insert5(float (&v)[KTOP], int (&ix)[KTOP],
                                        float nv, int ni) {
    if (!better(nv, ni, v[KTOP - 1], ix[KTOP - 1])) return;
    v[KTOP - 1] = nv;
    ix[KTOP - 1] = ni;
#pragma unroll
    for (int j = KTOP - 1; j > 0; --j) {
        if (better(v[j], ix[j], v[j - 1], ix[j - 1])) {
            float tv = v[j]; v[j] = v[j - 1]; v[j - 1] = tv;
            int   ti = ix[j]; ix[j] = ix[j - 1]; ix[j - 1] = ti;
        } else {
            break;
        }
    }
}

__device__ __forceinline__ void warp_merge_step(float (&v)[KTOP], int (&ix)[KTOP],
                                                int off) {
    float ov[KTOP];
    int   oi[KTOP];
#pragma unroll
    for (int j = 0; j < KTOP; ++j) {
        ov[j] = __shfl_xor_sync(0xFFFFFFFFu, v[j], off);
        oi[j] = __shfl_xor_sync(0xFFFFFFFFu, ix[j], off);
    }
#pragma unroll
    for (int j = 0; j < KTOP; ++j) insert5(v, ix, ov[j], oi[j]);
}

__device__ __forceinline__ float max4(float4 z) {
    return fmaxf(fmaxf(z.x, z.y), fmaxf(z.z, z.w));
}

// Cap regs at 32/thread so 4 CTAs (64 warps) fit per SM.
__global__ __launch_bounds__(NTHREADS, 4)
void fused_topk_attn_kernel(const float* __restrict__ sp_z,
                            const float* __restrict__ sp_w,
                            const float* __restrict__ encoded,
                            float* __restrict__ out,       // [B, DIM]
                            float* __restrict__ attn_out,  // [B, KTOP] or nullptr
                            float* __restrict__ idx_out,   // [B, KTOP] or nullptr
                            int V) {
    const int row  = blockIdx.x;
    const int tid  = threadIdx.x;
    const int lane = tid & 31;
    const int warp = tid >> 5;

    __shared__ float s_warpmax[NWARPS];
    __shared__ float s_t;
    __shared__ int   s_gcnt;
    __shared__ int   s_cnt;
    __shared__ int   s_gbase[GRP_MAX];
    __shared__ float s_cand_v[CAND_MAX];
    __shared__ int   s_cand_i[CAND_MAX];
    __shared__ int   s_idx[KTOP];
    __shared__ float s_red[NWARPS][KTOP];
    __shared__ float s_scores[KTOP];

    if (tid == 0) { s_gcnt = 0; s_cnt = 0; }

    const size_t rowbase = (size_t)row * (size_t)V;
    const float4* zrow   = reinterpret_cast<const float4*>(sp_z + rowbase);
    const int nv4 = V >> 2;            // V % 4 == 0 for this problem (50000)

    // ---- 1. Threshold: 5th-largest warp-max over the first 2048 float4s ----
    // The top-5 warp-maxes are 5 distinct elements, so t <= global 5th:
    // filtering with (z >= t) provably keeps every global top-5 element.
    float tmax = NEG_INF;
#pragma unroll
    for (int g = 0; g < 4; ++g) {
        const int i = g * NTHREADS + tid;
        if (i < nv4) tmax = fmaxf(tmax, max4(__ldg(zrow + i)));
    }
#pragma unroll
    for (int off = 16; off; off >>= 1)
        tmax = fmaxf(tmax, __shfl_xor_sync(0xFFFFFFFFu, tmax, off));
    if (lane == 0) s_warpmax[warp] = tmax;
    __syncthreads();

    if (warp == 0) {
        float wv = (lane < NWARPS) ? s_warpmax[lane] : NEG_INF;
        float tcur = NEG_INF;
#pragma unroll
        for (int r = 0; r < KTOP; ++r) {
            float m = wv;
#pragma unroll
            for (int off = 16; off; off >>= 1)
                m = fmaxf(m, __shfl_xor_sync(0xFFFFFFFFu, m, off));
            unsigned msk = __ballot_sync(0xFFFFFFFFu, wv == m);
            int leader = __ffs(msk) - 1;
            if (lane == leader) wv = NEG_INF;   // remove exactly one holder
            tcur = m;
        }
        if (lane == 0) s_t = tcur;
    }
    __syncthreads();
    const float t = s_t;

    // ---- 2. Hot loop: 4 independent LDG.128 in flight, one predicated push ----
    const int nfull = nv4 / PER_ITER;
    for (int it = 0; it < nfull; ++it) {
        const int base = it * PER_ITER + tid;
        float4 z0 = __ldcs(zrow + base);
        float4 z1 = __ldcs(zrow + base +     NTHREADS);
        float4 z2 = __ldcs(zrow + base + 2 * NTHREADS);
        float4 z3 = __ldcs(zrow + base + 3 * NTHREADS);
        const float m = fmaxf(fmaxf(max4(z0), max4(z1)),
                              fmaxf(max4(z2), max4(z3)));
        if (m >= t) {                        // rare; body is 3 instrs, no sorting
            int p = atomicAdd(&s_gcnt, 1);
            if (p < GRP_MAX) s_gbase[p] = base;
        }
    }
    // Tail float4s: push surviving elements directly as candidates.
    for (int i = nfull * PER_ITER + tid; i < nv4; i += NTHREADS) {
        float4 z = __ldcs(zrow + i);
        if (max4(z) >= t) {
            const float zz[4] = {z.x, z.y, z.z, z.w};
#pragma unroll
            for (int r = 0; r < 4; ++r) {
                if (zz[r] >= t) {
                    int p = atomicAdd(&s_cnt, 1);
                    if (p < CAND_MAX) { s_cand_v[p] = zz[r]; s_cand_i[p] = (i << 2) + r; }
                }
            }
        }
    }
    __syncthreads();

    // ---- 3. Expand hit groups (16 elems on lanes 0..15): ballot-compact ----
    {
        const int ng = min(s_gcnt, GRP_MAX);
        for (int g = warp; g < ng; g += NWARPS) {
            const int base = s_gbase[g];
            float z = NEG_INF;
            int eidx = 0;
            if (lane < 16) {
                const int q = lane >> 2, r = lane & 3;
                const int fi = base + q * NTHREADS;      // float4 index
                eidx = (fi << 2) + r;
                z = __ldg(sp_z + rowbase + eidx);
            }
            const unsigned msk = __ballot_sync(0xFFFFFFFFu, z >= t);
            const int cnt = __popc(msk);
            int posbase = 0;
            if (lane == 0 && cnt) posbase = atomicAdd(&s_cnt, cnt);
            posbase = __shfl_sync(0xFFFFFFFFu, posbase, 0);
            const int off = __popc(msk & ((1u << lane) - 1));
            if ((z >= t) && (posbase + off) < CAND_MAX) {
                s_cand_v[posbase + off] = z;
                s_cand_i[posbase + off] = eidx;
            }
        }
    }
    __syncthreads();

    // ---- 4. Exact top-5 (with lax.top_k tie-break) over ~30 candidates ----
    if (warp == 0) {
        float v[KTOP];
        int   ix[KTOP];
#pragma unroll
        for (int k = 0; k < KTOP; ++k) { v[k] = NEG_INF; ix[k] = 0x7FFFFFFF; }
        const int n = min(s_cnt, CAND_MAX);
        for (int c = lane; c < n; c += 32)
            insert5(v, ix, s_cand_v[c], s_cand_i[c]);
#pragma unroll
        for (int off = 16; off; off >>= 1) warp_merge_step(v, ix, off);
        if (lane == 0) {
#pragma unroll
            for (int k = 0; k < KTOP; ++k) s_idx[k] = ix[k];
        }
    }
    __syncthreads();

    // ---------------- Phase 2: gather + attention ----------------
    const int d = tid;   // DIM == NTHREADS == 512
    const float enc = __ldg(encoded + (size_t)row * DIM + d);

    float w[KTOP];
    float partial[KTOP];
#pragma unroll
    for (int k = 0; k < KTOP; ++k) {
        w[k] = __ldg(sp_w + (size_t)s_idx[k] * DIM + d);
        partial[k] = w[k] * enc;
    }
#pragma unroll
    for (int off = 16; off; off >>= 1) {
#pragma unroll
        for (int k = 0; k < KTOP; ++k)
            partial[k] += __shfl_down_sync(0xFFFFFFFFu, partial[k], off);
    }
    if (lane == 0) {
#pragma unroll
        for (int k = 0; k < KTOP; ++k) s_red[warp][k] = partial[k];
    }
    __syncthreads();
    if (tid < KTOP) {
        float s = 0.f;
#pragma unroll
        for (int wq = 0; wq < NWARPS; ++wq) s += s_red[wq][tid];
        s_scores[tid] = s;
    }
    __syncthreads();

    float sc[KTOP];
#pragma unroll
    for (int k = 0; k < KTOP; ++k) sc[k] = s_scores[k];
    float mx = sc[0];
#pragma unroll
    for (int k = 1; k < KTOP; ++k) mx = fmaxf(mx, sc[k]);
    float e[KTOP];
    float esum = 0.f;
#pragma unroll
    for (int k = 0; k < KTOP; ++k) { e[k] = expf(sc[k] - mx); esum += e[k]; }
    const float inv = 1.0f / esum;

    float acc = 0.f;
#pragma unroll
    for (int k = 0; k < KTOP; ++k) acc += w[k] * (e[k] * inv);
    out[(size_t)row * DIM + d] = acc;

    if (tid < KTOP) {
        if (attn_out) attn_out[(size_t)row * KTOP + tid] = e[tid] * inv;
        if (idx_out)  idx_out[(size_t)row * KTOP + tid] = (float)s_idx[tid];
    }
}

extern "C" void kernel_launch(void* const* d_in, const int* in_sizes, int n_in,
                              void* d_out, int out_size) {
    const float* sp_z    = (const float*)d_in[0];  // [B, V]
    const float* sp_w    = (const float*)d_in[1];  // [V, DIM]
    const float* encoded = (const float*)d_in[2];  // [B, DIM]

    const int B = in_sizes[2] / DIM;
    const int V = in_sizes[0] / B;

    float* out = (float*)d_out;
    float* attn_out = nullptr;
    float* idx_out  = nullptr;
    if (out_size >= B * (DIM + KTOP))     attn_out = out + (size_t)B * DIM;
    if (out_size >= B * (DIM + 2 * KTOP)) idx_out  = out + (size_t)B * (DIM + KTOP);

    fused_topk_attn_kernel<<<B, NTHREADS>>>(sp_z, sp_w, encoded,
                                            out, attn_out, idx_out, V);
}